// round 17
// baseline (speedup 1.0000x reference)
#include <cuda_runtime.h>
#include <cuda_fp16.h>

#define XSB 144              // x smem row stride, bytes (72 halves)
#define CS  100              // epilogue row stride, floats (96 + pad)

#define SMEM_TOTAL 16128     // x: 112*144 bytes; epilogue needs 32*100*4=12800, reuses

// w fragments, mma-register order: [chunk][q][lane] as uint4 per lane.
// 64 real chunks + 2 pad chunks so distance-2 prefetch needs no bounds check.
__device__ __align__(16) unsigned g_wf[66*4*128];

__global__ void prep_w(const float* w) {
    int idx = blockIdx.x*256 + threadIdx.x;       // 32768 entries
    int r = idx & 3, lane = (idx >> 2) & 31, q = (idx >> 7) & 3;
    int cc = (idx >> 9) & 3, k = idx >> 11;
    int f = q*16 + (r >> 1)*8 + (lane >> 2);
    int c = cc*16 + (r & 1)*8 + 2*(lane & 3);
    // input layout [f][c][k]
    __half lo = __float2half_rn(w[f*1024 + c*16 + k]);
    __half hi = __float2half_rn(w[f*1024 + (c+1)*16 + k]);
    g_wf[idx] = ((unsigned)__half_as_ushort(hi) << 16) | __half_as_ushort(lo);
}

__device__ __forceinline__ void ldsm4(unsigned* r, unsigned a) {
    asm volatile("ldmatrix.sync.aligned.m8n8.x4.shared.b16 {%0,%1,%2,%3}, [%4];"
        : "=r"(r[0]), "=r"(r[1]), "=r"(r[2]), "=r"(r[3]) : "r"(a));
}
__device__ __forceinline__ void mma16(float* c, const unsigned* a, const unsigned* b) {
    asm volatile("mma.sync.aligned.m16n8k16.row.col.f32.f16.f16.f32 "
        "{%0,%1,%2,%3},{%4,%5,%6,%7},{%8,%9},{%0,%1,%2,%3};"
        : "+f"(c[0]), "+f"(c[1]), "+f"(c[2]), "+f"(c[3])
        : "r"(a[0]), "r"(a[1]), "r"(a[2]), "r"(a[3]), "r"(b[0]), "r"(b[1]));
}

extern __shared__ unsigned char smraw[];

__global__ void __launch_bounds__(128, 5)
conv_main(const float* __restrict__ x, const float* __restrict__ bias, float* __restrict__ out) {
    const int t0 = blockIdx.x * 96;
    const int n  = blockIdx.y;
    const int tid = threadIdx.x;
    unsigned sb;
    asm("{.reg .u64 t; cvta.to.shared.u64 t,%1; cvt.u32.u64 %0,t;}" : "=r"(sb) : "l"(smraw));

    // x window [112 t][64 c], fp16
    const float* xb = x + n*64*4096;
    for (int i = tid; i < 64*112; i += 128) {
        int c = i / 112, t = i - c*112;
        int tg = t0 + t;
        float v = (tg < 4096) ? xb[c*4096 + tg] : 0.f;
        *(__half*)(smraw + t*XSB + c*2) = __float2half_rn(v);
    }

    const int wid = tid >> 5, lane = tid & 31;
    const int wm = wid >> 1, wn = wid & 1;        // 4 warps: 2(t) x 2(f); warp = 48t x 32f
    const unsigned aoff = (lane & 15)*XSB + (lane >> 4)*16;
    // warp's B records: q in {wn*2, wn*2+1}
    const uint4* wp = ((const uint4*)g_wf) + wn*64 + lane;
    float acc[3][4][4] = {};

    // B parity double-buffer (chunk j uses bb[j&1]); prefetch distance 2
    unsigned bb[2][8];
    #pragma unroll
    for (int q = 0; q < 2; q++) *(uint4*)&bb[0][q*4] = __ldg(wp + q*32);
    wp += 128;
    #pragma unroll
    for (int q = 0; q < 2; q++) *(uint4*)&bb[1][q*4] = __ldg(wp + q*32);
    wp += 128;                                    // wp -> chunk 2

    __syncthreads();                              // x ready; no barriers in loop

    for (int k = 0; k < 16; k++) {
        unsigned xh = sb + (wm*48 + k)*XSB + aoff;
        #pragma unroll
        for (int cc = 0; cc < 4; cc++) {
            const int cur = cc & 1;
            unsigned ah[3][4];
            ldsm4(ah[0], xh + cc*32);
            ldsm4(ah[1], xh + 16*XSB + cc*32);
            ldsm4(ah[2], xh + 32*XSB + cc*32);
            #pragma unroll
            for (int nt = 0; nt < 4; nt++) {
                const unsigned* b = &bb[cur][(nt >> 1)*4 + (nt & 1)*2];
                mma16(acc[0][nt], ah[0], b);
                mma16(acc[1][nt], ah[1], b);
                mma16(acc[2][nt], ah[2], b);
            }
            // refill this parity's B, 2 chunks ahead (pad chunks: branch-free)
            #pragma unroll
            for (int q = 0; q < 2; q++)
                *(uint4*)&bb[cur][q*4] = __ldg(wp + q*32);
            wp += 128;
        }
    }

    // epilogue: 2 passes of 32 f through smem (reuses x region)
    float* csm = (float*)smraw;                   // [32][CS]
    float* ob = out + n*64*4081;
    const int g = lane >> 2, tq = lane & 3;
    #pragma unroll
    for (int p = 0; p < 2; p++) {
        __syncthreads();                          // prev readers done
        if (wn == p) {
            #pragma unroll
            for (int mt = 0; mt < 3; mt++)
                #pragma unroll
                for (int nt = 0; nt < 4; nt++) {
                    int fl = nt*8 + 2*tq;
                    int r = wm*48 + mt*16 + g;
                    csm[fl*CS + r]         = acc[mt][nt][0];
                    csm[(fl+1)*CS + r]     = acc[mt][nt][1];
                    csm[fl*CS + r + 8]     = acc[mt][nt][2];
                    csm[(fl+1)*CS + r + 8] = acc[mt][nt][3];
                }
        }
        __syncthreads();
        for (int i = tid; i < 32*96; i += 128) {
            int f = i / 96, t = i - f*96;
            int tg = t0 + t;
            if (tg < 4081) ob[(p*32 + f)*4081 + tg] = csm[f*CS + t] + __ldg(bias + p*32 + f);
        }
    }
}

extern "C" void kernel_launch(void* const* d_in, const int* in_sizes, int n_in,
                              void* d_out, int out_size) {
    const float* x = (const float*)d_in[0];
    const float* w = (const float*)d_in[1];
    const float* b = (const float*)d_in[2];
    float* out = (float*)d_out;
    (void)in_sizes; (void)n_in; (void)out_size;

    cudaFuncSetAttribute(conv_main, cudaFuncAttributeMaxDynamicSharedMemorySize, SMEM_TOTAL);
    prep_w<<<128, 256>>>(w);
    conv_main<<<dim3(43, 64), 128, SMEM_TOTAL>>>(x, b, out);
}